// round 12
// baseline (speedup 1.0000x reference)
#include <cuda_runtime.h>
#include <cuda_fp16.h>
#include <cstdint>
#include <cstddef>

#define N_TOK 8192
#define DIM   256

// ---------------- device scratch ----------------
__device__ __half g_wqh[DIM * DIM];                  // Wq fp16
__device__ __half g_wkt[DIM * DIM];                  // Wk^T fp16
__device__ __half g_hh[N_TOK * DIM];                 // h  fp16
__device__ __half g_t[N_TOK * DIM];                  // t = h@Wk fp16
__device__ __half g_gh[N_TOK * DIM];                 // (h@M^T)/16 fp16
__device__ __half g_E[(size_t)N_TOK * N_TOK];        // exp(e - 4)  (128 MB, ~L2-resident)
__device__ float  g_l[N_TOK];
__device__ float  g_colsum[N_TOK];
__device__ int    g_cnt[32];                         // per-256-row-block completion counters

// ---------------- helpers ----------------
__device__ __forceinline__ uint32_t smem_u32(const void* p) {
    uint32_t a;
    asm("{ .reg .u64 t; cvta.to.shared.u64 t, %1; cvt.u32.u64 %0, t; }" : "=r"(a) : "l"(p));
    return a;
}
#define CP_ASYNC16(dst, src) \
    asm volatile("cp.async.cg.shared.global [%0], [%1], 16;" :: "r"(dst), "l"(src) : "memory")
#define CP_COMMIT()   asm volatile("cp.async.commit_group;" ::: "memory")
#define CP_WAIT(n)    asm volatile("cp.async.wait_group %0;" :: "n"(n) : "memory")

__device__ __forceinline__ void mma_f16acc(uint32_t c[2], uint32_t a0, uint32_t a1,
                                           uint32_t a2, uint32_t a3,
                                           uint32_t b0, uint32_t b1) {
    asm volatile(
        "mma.sync.aligned.m16n8k16.row.col.f16.f16.f16.f16 "
        "{%0,%1}, {%2,%3,%4,%5}, {%6,%7}, {%0,%1};"
        : "+r"(c[0]), "+r"(c[1])
        : "r"(a0), "r"(a1), "r"(a2), "r"(a3), "r"(b0), "r"(b1));
}
__device__ __forceinline__ void mma_f32acc(float c[4], uint32_t a0, uint32_t a1,
                                           uint32_t a2, uint32_t a3,
                                           uint32_t b0, uint32_t b1) {
    asm volatile(
        "mma.sync.aligned.m16n8k16.row.col.f32.f16.f16.f32 "
        "{%0,%1,%2,%3}, {%4,%5,%6,%7}, {%8,%9}, {%0,%1,%2,%3};"
        : "+f"(c[0]), "+f"(c[1]), "+f"(c[2]), "+f"(c[3])
        : "r"(a0), "r"(a1), "r"(a2), "r"(a3), "r"(b0), "r"(b1));
}
__device__ __forceinline__ void ldsm_x4(uint32_t& r0, uint32_t& r1, uint32_t& r2,
                                        uint32_t& r3, uint32_t addr) {
    asm volatile("ldmatrix.sync.aligned.m8n8.x4.shared.b16 {%0,%1,%2,%3}, [%4];"
                 : "=r"(r0), "=r"(r1), "=r"(r2), "=r"(r3) : "r"(addr));
}
#define STSM_X4(addr, r0, r1, r2, r3) \
    asm volatile("stmatrix.sync.aligned.m8n8.x4.shared.b16 [%0], {%1,%2,%3,%4};" \
                 :: "r"(addr), "r"(r0), "r"(r1), "r"(r2), "r"(r3) : "memory")

__device__ __forceinline__ uint32_t ex2_f16x2(__half2 t) {
    uint32_t r;
    asm("ex2.approx.f16x2 %0, %1;" : "=r"(r) : "r"(*(const uint32_t*)&t));
    return r;
}

// ---------------- convert h->fp16, init accums/counters, prep weights --------
__global__ void half_convert_init(const float* __restrict__ h,
                                  const float* __restrict__ Wq,
                                  const float* __restrict__ Wk,
                                  __half* __restrict__ hh,
                                  float* __restrict__ out) {
    __shared__ float tile[32][33];
    int i = blockIdx.x * 256 + threadIdx.x;
    float4 v = ((const float4*)h)[i];
    ((__half2*)hh)[2 * i]     = __floats2half2_rn(v.x, v.y);
    ((__half2*)hh)[2 * i + 1] = __floats2half2_rn(v.z, v.w);
    if (i < N_TOK) { g_l[i] = 0.f; g_colsum[i] = 0.f; }
    if (i < DIM)   out[i] = 0.f;
    if (i < 32)    g_cnt[i] = 0;

    if (blockIdx.x < 64) {
        int t = threadIdx.x, tx = t & 31, ty = t >> 5;
        int bx = blockIdx.x & 7, by = blockIdx.x >> 3;
#pragma unroll
        for (int r = 0; r < 32; r += 8)
            tile[ty + r][tx] = Wk[(by * 32 + ty + r) * DIM + bx * 32 + tx];
        __syncthreads();
#pragma unroll
        for (int r = 0; r < 32; r += 8)
            g_wkt[(bx * 32 + ty + r) * DIM + by * 32 + tx] = __float2half(tile[tx][ty + r]);
        int idx = blockIdx.x * 1024 + t * 4;
        float4 w = *(const float4*)(Wq + idx);
        *(__half2*)(g_wqh + idx)     = __floats2half2_rn(w.x, w.y);
        *(__half2*)(g_wqh + idx + 2) = __floats2half2_rn(w.z, w.w);
    }
}

// =================== shared tiling constants ===================
static constexpr int ROW_H = 72;

// ---------------- generic HMMA NT GEMM: C = (A @ B^T) * scale (fp32 acc) -----
static constexpr int GT_HALF = 128 * ROW_H;
static constexpr int GSTAGE  = 2 * GT_HALF;
static constexpr int GSMEM   = 2 * GSTAGE * 2;      // 73728 B

__global__ void __launch_bounds__(256, 2)
hgemm_nt(const __half* __restrict__ A0, const __half* __restrict__ B0,
         __half* __restrict__ C, float scale) {
    extern __shared__ __align__(16) __half sm[];
    const int tid  = threadIdx.x;
    const int lane = tid & 31;
    const int wid  = tid >> 5;
    const int warpM = (wid & 1) * 64;
    const int warpN = (wid >> 1) * 32;
    const int blockRow = blockIdx.y * 128;
    const int blockCol = blockIdx.x * 128;

    const __half* Aglob = A0 + (size_t)blockRow * DIM;
    const __half* Bglob = B0 + (size_t)blockCol * DIM;
    const uint32_t smb = smem_u32(sm);

    const int lm = tid >> 3;
    const int lq = tid & 7;
    auto prefetch = [&](int kc, int stage) {
        const int kof = kc * 64;
#pragma unroll
        for (int i = 0; i < 4; i++) {
            int m = lm + i * 32;
            uint32_t d = smb + (uint32_t)(stage * GSTAGE + m * ROW_H + lq * 8) * 2;
            CP_ASYNC16(d, Aglob + (size_t)m * DIM + kof + lq * 8);
        }
#pragma unroll
        for (int i = 0; i < 4; i++) {
            int m = lm + i * 32;
            uint32_t d = smb + (uint32_t)(stage * GSTAGE + GT_HALF + m * ROW_H + lq * 8) * 2;
            CP_ASYNC16(d, Bglob + (size_t)m * DIM + kof + lq * 8);
        }
        CP_COMMIT();
    };

    const int laneA_row = lane & 15;
    const int laneA_k   = (lane >> 4) * 8;
    const int laneB_n   = (lane & 7) + ((lane >> 4) << 3);
    const int laneB_k   = ((lane >> 3) & 1) * 8;

    float acc[4][4][4];
#pragma unroll
    for (int mt = 0; mt < 4; mt++)
#pragma unroll
        for (int nt = 0; nt < 4; nt++)
#pragma unroll
            for (int p = 0; p < 4; p++) acc[mt][nt][p] = 0.f;

    prefetch(0, 0);

#pragma unroll 1
    for (int kc = 0; kc < 4; kc++) {
        const int stage = kc & 1;
        if (kc < 3) { prefetch(kc + 1, stage ^ 1); CP_WAIT(1); }
        else        { CP_WAIT(0); }
        __syncthreads();

        const uint32_t Asb = smb + (uint32_t)(stage * GSTAGE) * 2;
        const uint32_t Bsb = Asb + (uint32_t)GT_HALF * 2;

#pragma unroll
        for (int s = 0; s < 4; s++) {
            uint32_t a[4][4];
#pragma unroll
            for (int mt = 0; mt < 4; mt++) {
                uint32_t addr = Asb + (uint32_t)((warpM + mt * 16 + laneA_row) * ROW_H
                                                 + s * 16 + laneA_k) * 2;
                ldsm_x4(a[mt][0], a[mt][1], a[mt][2], a[mt][3], addr);
            }
            uint32_t b[4][2];
#pragma unroll
            for (int np = 0; np < 2; np++) {
                uint32_t addr = Bsb + (uint32_t)((warpN + np * 16 + laneB_n) * ROW_H
                                                 + s * 16 + laneB_k) * 2;
                ldsm_x4(b[2 * np][0], b[2 * np][1], b[2 * np + 1][0], b[2 * np + 1][1], addr);
            }
#pragma unroll
            for (int mt = 0; mt < 4; mt++)
#pragma unroll
                for (int nt = 0; nt < 4; nt++)
                    mma_f32acc(acc[mt][nt], a[mt][0], a[mt][1], a[mt][2], a[mt][3],
                               b[nt][0], b[nt][1]);
        }
        __syncthreads();
    }

    const int r0 = blockRow + warpM + (lane >> 2);
    const int c0 = blockCol + warpN + 2 * (lane & 3);
#pragma unroll
    for (int mt = 0; mt < 4; mt++)
#pragma unroll
        for (int nt = 0; nt < 4; nt++) {
            const int row = r0 + mt * 16;
            const int col = c0 + nt * 8;
            *(__half2*)(C + (size_t)row * DIM + col) =
                __floats2half2_rn(acc[mt][nt][0] * scale, acc[mt][nt][1] * scale);
            *(__half2*)(C + (size_t)(row + 8) * DIM + col) =
                __floats2half2_rn(acc[mt][nt][2] * scale, acc[mt][nt][3] * scale);
        }
}

// ---------------- fused attention-score + column-sum kernel ----------------
// bids [0,2048): attn tiles 256x128 (as R11). bids [2048,2560): colsum CTAs that
// spin-wait on per-row-block counters, then reduce L2-hot E.
static constexpr int AT_A_HALF = 256 * ROW_H;
static constexpr int AT_B_HALF = 128 * ROW_H;
static constexpr int ASTAGE    = AT_A_HALF + AT_B_HALF;
static constexpr int ASMEM     = 2 * ASTAGE * 2;          // 110592 B
static constexpr int WST_ROW   = 72;                      // warp staging row (halves)

__global__ void __launch_bounds__(256, 2)
attn_fused_kernel() {
    extern __shared__ __align__(16) __half sm[];
    const int bid = blockIdx.x;
    const int tid = threadIdx.x;

    // ================= colsum consumer CTAs =================
    if (bid >= 2048) {
        const int cid = bid - 2048;
        const int yb  = cid >> 2;            // 64-row block, 0..127 (ascending = completion order)
        const int jg  = cid & 3;
        if (tid == 0) {
            while (atomicAdd(&g_cnt[yb >> 2], 0) < 64) __nanosleep(512);
        }
        __syncthreads();
        __threadfence();

        float* inv_s = (float*)sm;
        const int i0 = yb * 64;
        if (tid < 64) inv_s[tid] = 1.f / g_l[i0 + tid];
        __syncthreads();

        const int j8 = jg * 256 + tid;
        const uint4* Ep = (const uint4*)g_E + (size_t)i0 * (N_TOK / 8) + j8;
        float a[8];
#pragma unroll
        for (int k = 0; k < 8; k++) a[k] = 0.f;
#pragma unroll 8
        for (int i = 0; i < 64; i++) {
            uint4 v = Ep[(size_t)i * (N_TOK / 8)];
            const float w = inv_s[i];
            const __half2* hp = (const __half2*)&v;
#pragma unroll
            for (int k = 0; k < 4; k++) {
                float2 f = __half22float2(hp[k]);
                a[2 * k]     = fmaf(f.x, w, a[2 * k]);
                a[2 * k + 1] = fmaf(f.y, w, a[2 * k + 1]);
            }
        }
#pragma unroll
        for (int k = 0; k < 8; k++)
            atomicAdd(&g_colsum[8 * j8 + k], a[k]);
        return;
    }

    // ================= attn producer CTAs =================
    const int lane = tid & 31;
    const int wid  = tid >> 5;
    const int warpM = (wid >> 1) * 64;
    const int warpN = (wid & 1) * 64;
    const int bx = bid & 63, by = bid >> 6;
    const int blockRow = by * 256;
    const int blockCol = bx * 128;

    const __half* Aglob = g_hh + (size_t)blockRow * DIM;
    const __half* Bglob = g_gh + (size_t)blockCol * DIM;
    const uint32_t smb = smem_u32(sm);

    const int lm = tid >> 3;
    const int lq = tid & 7;
    auto prefetch = [&](int kc, int stage) {
        const int kof = kc * 64;
#pragma unroll
        for (int i = 0; i < 8; i++) {
            int m = lm + i * 32;
            uint32_t d = smb + (uint32_t)(stage * ASTAGE + m * ROW_H + lq * 8) * 2;
            CP_ASYNC16(d, Aglob + (size_t)m * DIM + kof + lq * 8);
        }
#pragma unroll
        for (int i = 0; i < 4; i++) {
            int m = lm + i * 32;
            uint32_t d = smb + (uint32_t)(stage * ASTAGE + AT_A_HALF + m * ROW_H + lq * 8) * 2;
            CP_ASYNC16(d, Bglob + (size_t)m * DIM + kof + lq * 8);
        }
        CP_COMMIT();
    };

    const int laneA_row = lane & 15;
    const int laneA_k   = (lane >> 4) * 8;
    const int laneB_n   = (lane & 7) + ((lane >> 4) << 3);
    const int laneB_k   = ((lane >> 3) & 1) * 8;

    uint32_t acc16[4][8][2];
#pragma unroll
    for (int mt = 0; mt < 4; mt++)
#pragma unroll
        for (int nt = 0; nt < 8; nt++) { acc16[mt][nt][0] = 0u; acc16[mt][nt][1] = 0u; }

    prefetch(0, 0);

#pragma unroll 1
    for (int kc = 0; kc < 4; kc++) {
        const int stage = kc & 1;
        if (kc < 3) { prefetch(kc + 1, stage ^ 1); CP_WAIT(1); }
        else        { CP_WAIT(0); }
        __syncthreads();

        const uint32_t Asb = smb + (uint32_t)(stage * ASTAGE) * 2;
        const uint32_t Bsb = Asb + (uint32_t)AT_A_HALF * 2;

#pragma unroll
        for (int s = 0; s < 4; s++) {
            uint32_t a[4][4];
#pragma unroll
            for (int mt = 0; mt < 4; mt++) {
                uint32_t addr = Asb + (uint32_t)((warpM + mt * 16 + laneA_row) * ROW_H
                                                 + s * 16 + laneA_k) * 2;
                ldsm_x4(a[mt][0], a[mt][1], a[mt][2], a[mt][3], addr);
            }
            uint32_t b[8][2];
#pragma unroll
            for (int np = 0; np < 4; np++) {
                uint32_t addr = Bsb + (uint32_t)((warpN + np * 16 + laneB_n) * ROW_H
                                                 + s * 16 + laneB_k) * 2;
                ldsm_x4(b[2 * np][0], b[2 * np][1], b[2 * np + 1][0], b[2 * np + 1][1], addr);
            }
#pragma unroll
            for (int mt = 0; mt < 4; mt++)
#pragma unroll
                for (int nt = 0; nt < 8; nt++)
                    mma_f16acc(acc16[mt][nt], a[mt][0], a[mt][1], a[mt][2], a[mt][3],
                               b[nt][0], b[nt][1]);
        }
        __syncthreads();
    }

    // ---------- epilogue: per-warp ex2 + stsm + warp-local coalesced stores ----
    // acc = logits (g pre-scaled by 1/16). E = 2^(acc*log2e - 4*log2e)
    const __half2 K2 = __floats2half2_rn(1.44269504f, 1.44269504f);
    const __half2 B2 = __floats2half2_rn(-5.77078016f, -5.77078016f);

    const int r8   = lane & 7;
    const int sel8 = ((lane >> 3) & 1) << 3;
    const int c8   = (lane >> 4) << 3;
    __half* wstage = sm + wid * (32 * WST_ROW);                // 36.9KB total (stage0 only)
    const uint32_t wstage_u = smb + (uint32_t)(wid * 32 * WST_ROW) * 2;

    float rowsum[8];
#pragma unroll
    for (int p = 0; p < 2; p++) {
#pragma unroll
        for (int mth = 0; mth < 2; mth++) {
            const int mt = 2 * p + mth;
            __half2 rsa = __floats2half2_rn(0.f, 0.f);
            __half2 rsb = rsa;
#pragma unroll
            for (int np = 0; np < 4; np++) {
                uint32_t e0 = ex2_f16x2(__hfma2(*(const __half2*)&acc16[mt][2*np][0],   K2, B2));
                uint32_t e1 = ex2_f16x2(__hfma2(*(const __half2*)&acc16[mt][2*np][1],   K2, B2));
                uint32_t e2 = ex2_f16x2(__hfma2(*(const __half2*)&acc16[mt][2*np+1][0], K2, B2));
                uint32_t e3 = ex2_f16x2(__hfma2(*(const __half2*)&acc16[mt][2*np+1][1], K2, B2));
                rsa = __hadd2(rsa, *(const __half2*)&e0);
                rsa = __hadd2(rsa, *(const __half2*)&e2);
                rsb = __hadd2(rsb, *(const __half2*)&e1);
                rsb = __hadd2(rsb, *(const __half2*)&e3);
                uint32_t addr = wstage_u +
                    (uint32_t)((mth * 16 + r8 + sel8) * WST_ROW + np * 16 + c8) * 2;
                STSM_X4(addr, e0, e1, e2, e3);
            }
            float2 fa = __half22float2(rsa);
            float2 fb = __half22float2(rsb);
            rowsum[2 * mt]     = fa.x + fa.y;
            rowsum[2 * mt + 1] = fb.x + fb.y;
        }
        __syncwarp();
        // store this pass's 32 rows (warp-local, coalesced 128B segments)
        const int lr8 = lane >> 3;
#pragma unroll
        for (int it = 0; it < 8; it++) {
            const int row = 4 * it + lr8;                      // 0..31
            uint4 v = *(const uint4*)(wstage + row * WST_ROW + (lane & 7) * 8);
            *(uint4*)(g_E + (size_t)(blockRow + warpM + 32 * p + row) * N_TOK
                      + blockCol + warpN + (lane & 7) * 8) = v;
        }
        __syncwarp();
    }

#pragma unroll
    for (int k = 0; k < 8; k++) {
        rowsum[k] += __shfl_xor_sync(0xFFFFFFFF, rowsum[k], 1);
        rowsum[k] += __shfl_xor_sync(0xFFFFFFFF, rowsum[k], 2);
    }
    if ((lane & 3) == 0) {
#pragma unroll
        for (int k = 0; k < 8; k++) {
            int row = blockRow + warpM + (lane >> 2) + (k >> 1) * 16 + (k & 1) * 8;
            atomicAdd(&g_l[row], rowsum[k]);
        }
    }

    // publish: all writes visible, then bump this row-block's counter
    __threadfence();
    __syncthreads();
    if (tid == 0) atomicAdd(&g_cnt[by], 1);
}

// ---------------- x = (colsum/N) @ h  (j-parallel, atomic merge) ------------
__global__ void out_kernel(const float* __restrict__ h, float* __restrict__ out) {
    __shared__ float cs[32];
    const int d = threadIdx.x;
    const int j0 = blockIdx.x * 32;
    if (d < 32) cs[d] = g_colsum[j0 + d];
    __syncthreads();
    float acc = 0.f;
#pragma unroll 8
    for (int j = 0; j < 32; j++)
        acc = fmaf(cs[j], h[(size_t)(j0 + j) * DIM + d], acc);
    atomicAdd(&out[d], acc * (1.0f / N_TOK));
}

// ---------------- launch ----------------
extern "C" void kernel_launch(void* const* d_in, const int* in_sizes, int n_in,
                              void* d_out, int out_size) {
    const float* h  = (const float*)d_in[0];
    const float* Wq = (const float*)d_in[1];
    const float* Wk = (const float*)d_in[2];
    float* out = (float*)d_out;

    __half *pHH, *pT, *pGH, *pWQ, *pWKT;
    cudaGetSymbolAddress((void**)&pHH,  g_hh);
    cudaGetSymbolAddress((void**)&pT,   g_t);
    cudaGetSymbolAddress((void**)&pGH,  g_gh);
    cudaGetSymbolAddress((void**)&pWQ,  g_wqh);
    cudaGetSymbolAddress((void**)&pWKT, g_wkt);

    cudaFuncSetAttribute(attn_fused_kernel, cudaFuncAttributeMaxDynamicSharedMemorySize, ASMEM);
    cudaFuncSetAttribute(hgemm_nt,          cudaFuncAttributeMaxDynamicSharedMemorySize, GSMEM);

    half_convert_init<<<2048, 256>>>(h, Wq, Wk, pHH, out);       // 1
    hgemm_nt<<<dim3(2, 64), 256, GSMEM>>>(pHH, pWKT, pT, 1.0f);  // 2: t = h@Wk
    hgemm_nt<<<dim3(2, 64), 256, GSMEM>>>(pT, pWQ, pGH, 0.0625f);// 3: g = (t@Wq^T)/16
    attn_fused_kernel<<<2560, 256, ASMEM>>>();                   // 4: E + rowsums + colsum
    out_kernel<<<256, 256>>>(h, out);                            // 5
}

// round 13
// speedup vs baseline: 1.0552x; 1.0552x over previous
#include <cuda_runtime.h>
#include <cuda_fp16.h>
#include <cstdint>
#include <cstddef>

#define N_TOK 8192
#define DIM   256

// ---------------- device scratch ----------------
__device__ __half g_wqh[DIM * DIM];                  // Wq fp16
__device__ __half g_wkt[DIM * DIM];                  // Wk^T fp16
__device__ __half g_hh[N_TOK * DIM];                 // h  fp16
__device__ __half g_t[N_TOK * DIM];                  // t = h@Wk fp16
__device__ __half g_gh[N_TOK * DIM];                 // (h@M^T)/16 fp16
__device__ __half g_E[(size_t)N_TOK * N_TOK];        // exp(e - 4)  (128 MB, ~L2-resident)
__device__ float  g_l[N_TOK];
__device__ float  g_colsum[N_TOK];

// ---------------- helpers ----------------
__device__ __forceinline__ uint32_t smem_u32(const void* p) {
    uint32_t a;
    asm("{ .reg .u64 t; cvta.to.shared.u64 t, %1; cvt.u32.u64 %0, t; }" : "=r"(a) : "l"(p));
    return a;
}
#define CP_ASYNC16(dst, src) \
    asm volatile("cp.async.cg.shared.global [%0], [%1], 16;" :: "r"(dst), "l"(src) : "memory")
#define CP_COMMIT()   asm volatile("cp.async.commit_group;" ::: "memory")
#define CP_WAIT(n)    asm volatile("cp.async.wait_group %0;" :: "n"(n) : "memory")

__device__ __forceinline__ void mma_f16acc(uint32_t c[2], uint32_t a0, uint32_t a1,
                                           uint32_t a2, uint32_t a3,
                                           uint32_t b0, uint32_t b1) {
    asm volatile(
        "mma.sync.aligned.m16n8k16.row.col.f16.f16.f16.f16 "
        "{%0,%1}, {%2,%3,%4,%5}, {%6,%7}, {%0,%1};"
        : "+r"(c[0]), "+r"(c[1])
        : "r"(a0), "r"(a1), "r"(a2), "r"(a3), "r"(b0), "r"(b1));
}
__device__ __forceinline__ void mma_f32acc(float c[4], uint32_t a0, uint32_t a1,
                                           uint32_t a2, uint32_t a3,
                                           uint32_t b0, uint32_t b1) {
    asm volatile(
        "mma.sync.aligned.m16n8k16.row.col.f32.f16.f16.f32 "
        "{%0,%1,%2,%3}, {%4,%5,%6,%7}, {%8,%9}, {%0,%1,%2,%3};"
        : "+f"(c[0]), "+f"(c[1]), "+f"(c[2]), "+f"(c[3])
        : "r"(a0), "r"(a1), "r"(a2), "r"(a3), "r"(b0), "r"(b1));
}
__device__ __forceinline__ void ldsm_x4(uint32_t& r0, uint32_t& r1, uint32_t& r2,
                                        uint32_t& r3, uint32_t addr) {
    asm volatile("ldmatrix.sync.aligned.m8n8.x4.shared.b16 {%0,%1,%2,%3}, [%4];"
                 : "=r"(r0), "=r"(r1), "=r"(r2), "=r"(r3) : "r"(addr));
}
#define STSM_X4(addr, r0, r1, r2, r3) \
    asm volatile("stmatrix.sync.aligned.m8n8.x4.shared.b16 [%0], {%1,%2,%3,%4};" \
                 :: "r"(addr), "r"(r0), "r"(r1), "r"(r2), "r"(r3) : "memory")

__device__ __forceinline__ uint32_t ex2_f16x2(__half2 t) {
    uint32_t r;
    asm("ex2.approx.f16x2 %0, %1;" : "=r"(r) : "r"(*(const uint32_t*)&t));
    return r;
}

// ---------------- convert h->fp16, init accums, prep weights ----------------
__global__ void half_convert_init(const float* __restrict__ h,
                                  const float* __restrict__ Wq,
                                  const float* __restrict__ Wk,
                                  __half* __restrict__ hh,
                                  float* __restrict__ out) {
    __shared__ float tile[32][33];
    int i = blockIdx.x * 256 + threadIdx.x;
    float4 v = ((const float4*)h)[i];
    ((__half2*)hh)[2 * i]     = __floats2half2_rn(v.x, v.y);
    ((__half2*)hh)[2 * i + 1] = __floats2half2_rn(v.z, v.w);
    if (i < N_TOK) { g_l[i] = 0.f; g_colsum[i] = 0.f; }
    if (i < DIM)   out[i] = 0.f;

    if (blockIdx.x < 64) {
        int t = threadIdx.x, tx = t & 31, ty = t >> 5;
        int bx = blockIdx.x & 7, by = blockIdx.x >> 3;
#pragma unroll
        for (int r = 0; r < 32; r += 8)
            tile[ty + r][tx] = Wk[(by * 32 + ty + r) * DIM + bx * 32 + tx];
        __syncthreads();
#pragma unroll
        for (int r = 0; r < 32; r += 8)
            g_wkt[(bx * 32 + ty + r) * DIM + by * 32 + tx] = __float2half(tile[tx][ty + r]);
        int idx = blockIdx.x * 1024 + t * 4;
        float4 w = *(const float4*)(Wq + idx);
        *(__half2*)(g_wqh + idx)     = __floats2half2_rn(w.x, w.y);
        *(__half2*)(g_wqh + idx + 2) = __floats2half2_rn(w.z, w.w);
    }
}

// =================== shared tiling constants ===================
static constexpr int ROW_H   = 72;
static constexpr int STG_ROW = 136;

// ---------------- generic HMMA NT GEMM: C = (A @ B^T) * scale (fp32 acc) -----
static constexpr int GT_HALF = 128 * ROW_H;
static constexpr int GSTAGE  = 2 * GT_HALF;
static constexpr int GSMEM   = 2 * GSTAGE * 2;      // 73728 B

__global__ void __launch_bounds__(256, 2)
hgemm_nt(const __half* __restrict__ A0, const __half* __restrict__ B0,
         __half* __restrict__ C, float scale) {
    extern __shared__ __align__(16) __half sm[];
    const int tid  = threadIdx.x;
    const int lane = tid & 31;
    const int wid  = tid >> 5;
    const int warpM = (wid & 1) * 64;
    const int warpN = (wid >> 1) * 32;
    const int blockRow = blockIdx.y * 128;
    const int blockCol = blockIdx.x * 128;

    const __half* Aglob = A0 + (size_t)blockRow * DIM;
    const __half* Bglob = B0 + (size_t)blockCol * DIM;
    const uint32_t smb = smem_u32(sm);

    const int lm = tid >> 3;
    const int lq = tid & 7;
    auto prefetch = [&](int kc, int stage) {
        const int kof = kc * 64;
#pragma unroll
        for (int i = 0; i < 4; i++) {
            int m = lm + i * 32;
            uint32_t d = smb + (uint32_t)(stage * GSTAGE + m * ROW_H + lq * 8) * 2;
            CP_ASYNC16(d, Aglob + (size_t)m * DIM + kof + lq * 8);
        }
#pragma unroll
        for (int i = 0; i < 4; i++) {
            int m = lm + i * 32;
            uint32_t d = smb + (uint32_t)(stage * GSTAGE + GT_HALF + m * ROW_H + lq * 8) * 2;
            CP_ASYNC16(d, Bglob + (size_t)m * DIM + kof + lq * 8);
        }
        CP_COMMIT();
    };

    const int laneA_row = lane & 15;
    const int laneA_k   = (lane >> 4) * 8;
    const int laneB_n   = (lane & 7) + ((lane >> 4) << 3);
    const int laneB_k   = ((lane >> 3) & 1) * 8;

    float acc[4][4][4];
#pragma unroll
    for (int mt = 0; mt < 4; mt++)
#pragma unroll
        for (int nt = 0; nt < 4; nt++)
#pragma unroll
            for (int p = 0; p < 4; p++) acc[mt][nt][p] = 0.f;

    prefetch(0, 0);

#pragma unroll 1
    for (int kc = 0; kc < 4; kc++) {
        const int stage = kc & 1;
        if (kc < 3) { prefetch(kc + 1, stage ^ 1); CP_WAIT(1); }
        else        { CP_WAIT(0); }
        __syncthreads();

        const uint32_t Asb = smb + (uint32_t)(stage * GSTAGE) * 2;
        const uint32_t Bsb = Asb + (uint32_t)GT_HALF * 2;

#pragma unroll
        for (int s = 0; s < 4; s++) {
            uint32_t a[4][4];
#pragma unroll
            for (int mt = 0; mt < 4; mt++) {
                uint32_t addr = Asb + (uint32_t)((warpM + mt * 16 + laneA_row) * ROW_H
                                                 + s * 16 + laneA_k) * 2;
                ldsm_x4(a[mt][0], a[mt][1], a[mt][2], a[mt][3], addr);
            }
            uint32_t b[4][2];
#pragma unroll
            for (int np = 0; np < 2; np++) {
                uint32_t addr = Bsb + (uint32_t)((warpN + np * 16 + laneB_n) * ROW_H
                                                 + s * 16 + laneB_k) * 2;
                ldsm_x4(b[2 * np][0], b[2 * np][1], b[2 * np + 1][0], b[2 * np + 1][1], addr);
            }
#pragma unroll
            for (int mt = 0; mt < 4; mt++)
#pragma unroll
                for (int nt = 0; nt < 4; nt++)
                    mma_f32acc(acc[mt][nt], a[mt][0], a[mt][1], a[mt][2], a[mt][3],
                               b[nt][0], b[nt][1]);
        }
        __syncthreads();
    }

    const int r0 = blockRow + warpM + (lane >> 2);
    const int c0 = blockCol + warpN + 2 * (lane & 3);
#pragma unroll
    for (int mt = 0; mt < 4; mt++)
#pragma unroll
        for (int nt = 0; nt < 4; nt++) {
            const int row = r0 + mt * 16;
            const int col = c0 + nt * 8;
            *(__half2*)(C + (size_t)row * DIM + col) =
                __floats2half2_rn(acc[mt][nt][0] * scale, acc[mt][nt][1] * scale);
            *(__half2*)(C + (size_t)(row + 8) * DIM + col) =
                __floats2half2_rn(acc[mt][nt][2] * scale, acc[mt][nt][3] * scale);
        }
}

// ---------------- fp16 mma.sync attention-score kernel ----------------
static constexpr int AT_A_HALF = 256 * ROW_H;
static constexpr int AT_B_HALF = 128 * ROW_H;
static constexpr int ASTAGE    = AT_A_HALF + AT_B_HALF;
static constexpr int ASMEM     = 2 * ASTAGE * 2;          // 110592 B

__global__ void __launch_bounds__(256, 2)
attn_kernel() {
    extern __shared__ __align__(16) __half sm[];
    const int tid  = threadIdx.x;
    const int lane = tid & 31;
    const int wid  = tid >> 5;
    const int warpM = (wid >> 1) * 64;
    const int warpN = (wid & 1) * 64;
    const int blockRow = blockIdx.y * 256;
    const int blockCol = blockIdx.x * 128;

    const __half* Aglob = g_hh + (size_t)blockRow * DIM;
    const __half* Bglob = g_gh + (size_t)blockCol * DIM;
    const uint32_t smb = smem_u32(sm);

    const int lm = tid >> 3;
    const int lq = tid & 7;
    auto prefetch = [&](int kc, int stage) {
        const int kof = kc * 64;
#pragma unroll
        for (int i = 0; i < 8; i++) {
            int m = lm + i * 32;
            uint32_t d = smb + (uint32_t)(stage * ASTAGE + m * ROW_H + lq * 8) * 2;
            CP_ASYNC16(d, Aglob + (size_t)m * DIM + kof + lq * 8);
        }
#pragma unroll
        for (int i = 0; i < 4; i++) {
            int m = lm + i * 32;
            uint32_t d = smb + (uint32_t)(stage * ASTAGE + AT_A_HALF + m * ROW_H + lq * 8) * 2;
            CP_ASYNC16(d, Bglob + (size_t)m * DIM + kof + lq * 8);
        }
        CP_COMMIT();
    };

    const int laneA_row = lane & 15;
    const int laneA_k   = (lane >> 4) * 8;
    const int laneB_n   = (lane & 7) + ((lane >> 4) << 3);
    const int laneB_k   = ((lane >> 3) & 1) * 8;

    uint32_t acc16[4][8][2];
#pragma unroll
    for (int mt = 0; mt < 4; mt++)
#pragma unroll
        for (int nt = 0; nt < 8; nt++) { acc16[mt][nt][0] = 0u; acc16[mt][nt][1] = 0u; }

    prefetch(0, 0);

#pragma unroll 1
    for (int kc = 0; kc < 4; kc++) {
        const int stage = kc & 1;
        if (kc < 3) { prefetch(kc + 1, stage ^ 1); CP_WAIT(1); }
        else        { CP_WAIT(0); }
        __syncthreads();

        const uint32_t Asb = smb + (uint32_t)(stage * ASTAGE) * 2;
        const uint32_t Bsb = Asb + (uint32_t)AT_A_HALF * 2;

#pragma unroll
        for (int s = 0; s < 4; s++) {
            uint32_t a[4][4];
#pragma unroll
            for (int mt = 0; mt < 4; mt++) {
                uint32_t addr = Asb + (uint32_t)((warpM + mt * 16 + laneA_row) * ROW_H
                                                 + s * 16 + laneA_k) * 2;
                ldsm_x4(a[mt][0], a[mt][1], a[mt][2], a[mt][3], addr);
            }
            uint32_t b[8][2];
#pragma unroll
            for (int np = 0; np < 4; np++) {
                uint32_t addr = Bsb + (uint32_t)((warpN + np * 16 + laneB_n) * ROW_H
                                                 + s * 16 + laneB_k) * 2;
                ldsm_x4(b[2 * np][0], b[2 * np][1], b[2 * np + 1][0], b[2 * np + 1][1], addr);
            }
#pragma unroll
            for (int mt = 0; mt < 4; mt++)
#pragma unroll
                for (int nt = 0; nt < 8; nt++)
                    mma_f16acc(acc16[mt][nt], a[mt][0], a[mt][1], a[mt][2], a[mt][3],
                               b[nt][0], b[nt][1]);
        }
        __syncthreads();
    }

    // ---------- epilogue: ex2.f16x2 + stmatrix staging + coalesced stores ----
    const __half2 K2 = __floats2half2_rn(1.44269504f, 1.44269504f);
    const __half2 B2 = __floats2half2_rn(-5.77078016f, -5.77078016f);

    const int r8   = lane & 7;
    const int sel8 = ((lane >> 3) & 1) << 3;
    const int c8   = (lane >> 4) << 3;
    const uint32_t st_base =
        smb + (uint32_t)((warpM + r8 + sel8) * STG_ROW + warpN + c8) * 2;

    float rowsum[8];
#pragma unroll
    for (int mt = 0; mt < 4; mt++) {
        __half2 rsa = __floats2half2_rn(0.f, 0.f);
        __half2 rsb = rsa;
#pragma unroll
        for (int np = 0; np < 4; np++) {
            uint32_t e0 = ex2_f16x2(__hfma2(*(const __half2*)&acc16[mt][2*np][0],   K2, B2));
            uint32_t e1 = ex2_f16x2(__hfma2(*(const __half2*)&acc16[mt][2*np][1],   K2, B2));
            uint32_t e2 = ex2_f16x2(__hfma2(*(const __half2*)&acc16[mt][2*np+1][0], K2, B2));
            uint32_t e3 = ex2_f16x2(__hfma2(*(const __half2*)&acc16[mt][2*np+1][1], K2, B2));
            rsa = __hadd2(rsa, *(const __half2*)&e0);
            rsa = __hadd2(rsa, *(const __half2*)&e2);
            rsb = __hadd2(rsb, *(const __half2*)&e1);
            rsb = __hadd2(rsb, *(const __half2*)&e3);
            uint32_t addr = st_base + (uint32_t)(mt * 16 * STG_ROW + np * 16) * 2;
            STSM_X4(addr, e0, e1, e2, e3);
        }
        float2 fa = __half22float2(rsa);
        float2 fb = __half22float2(rsb);
        rowsum[2 * mt]     = fa.x + fa.y;
        rowsum[2 * mt + 1] = fb.x + fb.y;
    }
#pragma unroll
    for (int k = 0; k < 8; k++) {
        rowsum[k] += __shfl_xor_sync(0xFFFFFFFF, rowsum[k], 1);
        rowsum[k] += __shfl_xor_sync(0xFFFFFFFF, rowsum[k], 2);
    }
    if ((lane & 3) == 0) {
#pragma unroll
        for (int k = 0; k < 8; k++) {
            int row = blockRow + warpM + (lane >> 2) + (k >> 1) * 16 + (k & 1) * 8;
            atomicAdd(&g_l[row], rowsum[k]);
        }
    }
    __syncthreads();

    // cooperative coalesced store: plain stores -> E stays L2-resident
#pragma unroll
    for (int it = 0; it < 16; it++) {
        int s = tid + it * 256;
        int row = s >> 4, q = s & 15;
        uint4 v = *(const uint4*)(sm + row * STG_ROW + q * 8);
        *(uint4*)(g_E + (size_t)(blockRow + row) * N_TOK + blockCol + q * 8) = v;
    }
}

// ---------------- column sums of normalized P -------------------------------
// REVERSE row-block order: last-written E rows are still L2-resident, so
// early colsum waves hit L2; forward order is the cyclic-LRU worst case.
__global__ void colsum_kernel() {
    __shared__ float inv_s[64];
    const int t = threadIdx.x;
    const int j8 = blockIdx.x * 256 + t;
    const int yb = 127 - (int)blockIdx.y;          // reversed traversal
    const int i0 = yb * 64;
    if (t < 64) inv_s[t] = 1.f / g_l[i0 + t];
    __syncthreads();

    const uint4* Ep = (const uint4*)g_E + (size_t)i0 * (N_TOK / 8) + j8;
    float a[8];
#pragma unroll
    for (int k = 0; k < 8; k++) a[k] = 0.f;
#pragma unroll 8
    for (int i = 0; i < 64; i++) {
        uint4 v = __ldcs(Ep + (size_t)i * (N_TOK / 8));
        const float w = inv_s[i];
        const __half2* hp = (const __half2*)&v;
#pragma unroll
        for (int k = 0; k < 4; k++) {
            float2 f = __half22float2(hp[k]);
            a[2 * k]     = fmaf(f.x, w, a[2 * k]);
            a[2 * k + 1] = fmaf(f.y, w, a[2 * k + 1]);
        }
    }
#pragma unroll
    for (int k = 0; k < 8; k++)
        atomicAdd(&g_colsum[8 * j8 + k], a[k]);
}

// ---------------- x = (colsum/N) @ h  (j-parallel, atomic merge) ------------
__global__ void out_kernel(const float* __restrict__ h, float* __restrict__ out) {
    __shared__ float cs[32];
    const int d = threadIdx.x;
    const int j0 = blockIdx.x * 32;
    if (d < 32) cs[d] = g_colsum[j0 + d];
    __syncthreads();
    float acc = 0.f;
#pragma unroll 8
    for (int j = 0; j < 32; j++)
        acc = fmaf(cs[j], h[(size_t)(j0 + j) * DIM + d], acc);
    atomicAdd(&out[d], acc * (1.0f / N_TOK));
}

// ---------------- launch ----------------
extern "C" void kernel_launch(void* const* d_in, const int* in_sizes, int n_in,
                              void* d_out, int out_size) {
    const float* h  = (const float*)d_in[0];
    const float* Wq = (const float*)d_in[1];
    const float* Wk = (const float*)d_in[2];
    float* out = (float*)d_out;

    __half *pHH, *pT, *pGH, *pWQ, *pWKT;
    cudaGetSymbolAddress((void**)&pHH,  g_hh);
    cudaGetSymbolAddress((void**)&pT,   g_t);
    cudaGetSymbolAddress((void**)&pGH,  g_gh);
    cudaGetSymbolAddress((void**)&pWQ,  g_wqh);
    cudaGetSymbolAddress((void**)&pWKT, g_wkt);

    cudaFuncSetAttribute(attn_kernel, cudaFuncAttributeMaxDynamicSharedMemorySize, ASMEM);
    cudaFuncSetAttribute(hgemm_nt,    cudaFuncAttributeMaxDynamicSharedMemorySize, GSMEM);

    half_convert_init<<<2048, 256>>>(h, Wq, Wk, pHH, out);       // 1
    hgemm_nt<<<dim3(2, 64), 256, GSMEM>>>(pHH, pWKT, pT, 1.0f);  // 2: t = h@Wk
    hgemm_nt<<<dim3(2, 64), 256, GSMEM>>>(pT, pWQ, pGH, 0.0625f);// 3: g = (t@Wq^T)/16
    attn_kernel<<<dim3(64, 32), 256, ASMEM>>>();                 // 4 (ncu slot)
    colsum_kernel<<<dim3(4, 128), 256>>>();                      // 5 (reverse order)
    out_kernel<<<256, 256>>>(h, out);                            // 6
}